// round 1
// baseline (speedup 1.0000x reference)
#include <cuda_runtime.h>
#include <cstdint>

#define BB 16
#define NN 25200
#define CC 85
#define NCLS 80
#define MAXDET 300
#define BINS 4096
#define CAP 4096
#define TARGET 2048
#define CONF_T 0.25f
#define IOU_T 0.45f
#define MAXWH 4096.0f

// Global scratch (no allocations allowed)
__device__ float  g_score[BB * NN];
__device__ float4 g_box[BB * NN];
__device__ int    g_cls[BB * NN];
__device__ int    g_idx[BB * NN];
__device__ int    g_cnt[BB];

__global__ void k_init() {
    if (threadIdx.x < BB) g_cnt[threadIdx.x] = 0;
}

// One warp per box: compute conf/argmax-class/box, filter, compact.
__global__ void k_prep(const float* __restrict__ pred) {
    int w    = (blockIdx.x * blockDim.x + threadIdx.x) >> 5;
    int lane = threadIdx.x & 31;
    if (w >= BB * NN) return;
    const float* p = pred + (long long)w * CC;
    float obj = __ldg(p + 4);

    float best = -1.0f;
    int   bj   = 0;
    #pragma unroll
    for (int c = lane; c < NCLS; c += 32) {
        float v = __ldg(p + 5 + c) * obj;   // same op order as reference: cls*obj then max
        if (v > best) { best = v; bj = c; } // strict > keeps earliest index within lane
    }
    #pragma unroll
    for (int o = 16; o; o >>= 1) {
        float ob = __shfl_down_sync(0xffffffffu, best, o);
        int   oj = __shfl_down_sync(0xffffffffu, bj, o);
        if (ob > best || (ob == best && oj < bj)) { best = ob; bj = oj; }
    }
    if (lane == 0 && obj > CONF_T && best > CONF_T) {
        int b = w / NN, n = w - b * NN;
        float x = p[0], y = p[1], ww = p[2], hh = p[3];
        float4 bx = make_float4(x - ww * 0.5f, y - hh * 0.5f,
                                x + ww * 0.5f, y + hh * 0.5f);
        int slot = atomicAdd(&g_cnt[b], 1);
        int gi   = b * NN + slot;
        g_score[gi] = best;
        g_box[gi]   = bx;
        g_cls[gi]   = bj;
        g_idx[gi]   = n;
    }
}

// One block per image: histogram -> gather top bins -> bitonic sort -> greedy NMS.
__global__ __launch_bounds__(1024, 1) void k_nms(float* __restrict__ out, int out_size) {
    extern __shared__ char smem[];
    int*                hist = (int*)smem;                                   // BINS ints
    unsigned long long* keys = (unsigned long long*)(smem + BINS * 4);       // CAP u64
    int*                sidx = (int*)(smem + BINS * 4 + CAP * 8);            // CAP ints
    float4*             kbox = (float4*)(smem + BINS * 4 + CAP * 8 + CAP * 4); // MAXDET
    float*              krow = (float*)(smem + BINS * 4 + CAP * 8 + CAP * 4 + MAXDET * 16); // MAXDET*6

    __shared__ int s_cnt, s_nk, s_T, s_top;

    int b = blockIdx.x, tid = threadIdx.x, bs = blockDim.x;
    int M = g_cnt[b];
    const float*  sc  = g_score + b * NN;
    const float4* bxp = g_box   + b * NN;
    const int*    clp = g_cls   + b * NN;
    const int*    idp = g_idx   + b * NN;

    for (int i = tid; i < BINS; i += bs) hist[i] = 0;
    if (tid == 0) { s_nk = 0; s_top = BINS - 1; }
    __syncthreads();

    for (int i = tid; i < M; i += bs) {
        float s  = sc[i];
        int bin  = (int)((s - CONF_T) * (BINS / 0.75f));
        bin = min(max(bin, 0), BINS - 1);
        atomicAdd(&hist[bin], 1);
    }
    __syncthreads();

    while (true) {
        // Pick bin range [T, s_top] covering ~TARGET candidates (cap CAP)
        if (tid == 0) {
            int T = s_top + 1, cum = 0;
            while (T > 0) {
                int c = hist[T - 1];
                if (cum > 0 && cum + c > CAP) break;
                cum += c;
                T--;
                if (cum >= TARGET) break;
            }
            s_T   = T;
            s_cnt = 0;
        }
        __syncthreads();
        int T = s_T;

        // Gather candidates in the selected bin range
        for (int i = tid; i < M; i += bs) {
            float s = sc[i];
            int bin = (int)((s - CONF_T) * (BINS / 0.75f));
            bin = min(max(bin, 0), BINS - 1);
            if (bin >= T && bin <= s_top) {
                int pth = atomicAdd(&s_cnt, 1);
                if (pth < CAP) {
                    keys[pth] = ((unsigned long long)__float_as_uint(s) << 32) |
                                (unsigned)(0xFFFFFFFFu - (unsigned)idp[i]);
                    sidx[pth] = i;
                }
            }
        }
        __syncthreads();
        int len = min(s_cnt, CAP);
        for (int i = len + tid; i < CAP; i += bs) keys[i] = 0ULL;
        __syncthreads();

        // Bitonic sort descending on (score_bits, ~idx)
        for (int k = 2; k <= CAP; k <<= 1) {
            for (int j = k >> 1; j > 0; j >>= 1) {
                for (int i = tid; i < CAP; i += bs) {
                    int ixj = i ^ j;
                    if (ixj > i) {
                        unsigned long long a = keys[i], c2 = keys[ixj];
                        bool sw = ((i & k) == 0) ? (a < c2) : (a > c2);
                        if (sw) {
                            keys[i] = c2; keys[ixj] = a;
                            int t = sidx[i]; sidx[i] = sidx[ixj]; sidx[ixj] = t;
                        }
                    }
                }
                __syncthreads();
            }
        }

        // Greedy NMS by warp 0 (lane-parallel IoU vs kept set)
        if (tid < 32) {
            int nk = s_nk;
            for (int c2 = 0; c2 < len && nk < MAXDET; c2++) {
                unsigned long long key = keys[c2];
                int i = sidx[c2];
                float4 bx = bxp[i];
                int j = clp[i];
                float off = (float)j * MAXWH;
                float x1 = bx.x + off, y1 = bx.y + off;
                float x2 = bx.z + off, y2 = bx.w + off;
                float area = (x2 - x1) * (y2 - y1);
                bool sup = false;
                for (int t = tid; t < nk; t += 32) {
                    float4 kb = kbox[t];
                    float xx1 = fmaxf(x1, kb.x), yy1 = fmaxf(y1, kb.y);
                    float xx2 = fminf(x2, kb.z), yy2 = fminf(y2, kb.w);
                    float iw = fmaxf(xx2 - xx1, 0.0f), ih = fmaxf(yy2 - yy1, 0.0f);
                    float inter = iw * ih;
                    float ka = (kb.z - kb.x) * (kb.w - kb.y);
                    float iou = inter / (area + ka - inter);
                    if (iou > IOU_T) { sup = true; break; }
                }
                sup = __any_sync(0xffffffffu, sup);
                if (!sup) {
                    if (tid == 0) {
                        kbox[nk] = make_float4(x1, y1, x2, y2);
                        float conf = __uint_as_float((unsigned)(key >> 32));
                        krow[nk * 6 + 0] = bx.x;
                        krow[nk * 6 + 1] = bx.y;
                        krow[nk * 6 + 2] = bx.z;
                        krow[nk * 6 + 3] = bx.w;
                        krow[nk * 6 + 4] = conf;
                        krow[nk * 6 + 5] = (float)j;
                    }
                    nk++;
                }
                __syncwarp(0xffffffffu);
            }
            if (tid == 0) s_nk = nk;
        }
        __syncthreads();
        if (tid == 0) s_top = s_T - 1;
        __syncthreads();
        if (s_nk >= MAXDET || s_T <= 0) break;
    }

    // Write output: rows [BB,300,6] then keeps [BB,300] (as 0/1 floats)
    int nk = s_nk;
    int base = b * MAXDET * 6;
    for (int k2 = tid; k2 < MAXDET; k2 += bs) {
        bool kp = (k2 < nk);
        #pragma unroll
        for (int c2 = 0; c2 < 6; c2++) {
            int o = base + k2 * 6 + c2;
            if (o < out_size) out[o] = kp ? krow[k2 * 6 + c2] : 0.0f;
        }
        int ko = BB * MAXDET * 6 + b * MAXDET + k2;
        if (ko < out_size) out[ko] = kp ? 1.0f : 0.0f;
    }
}

extern "C" void kernel_launch(void* const* d_in, const int* in_sizes, int n_in,
                              void* d_out, int out_size) {
    const float* pred = (const float*)d_in[0];
    float* out = (float*)d_out;

    k_init<<<1, 32>>>();

    int total_threads = BB * NN * 32;
    int threads = 256;
    int blocks = (total_threads + threads - 1) / threads;
    k_prep<<<blocks, threads>>>(pred);

    size_t smem = (size_t)BINS * 4 + (size_t)CAP * 8 + (size_t)CAP * 4 +
                  (size_t)MAXDET * 16 + (size_t)MAXDET * 6 * 4;
    cudaFuncSetAttribute(k_nms, cudaFuncAttributeMaxDynamicSharedMemorySize, (int)smem);
    k_nms<<<BB, 1024, smem>>>(out, out_size);
}